// round 10
// baseline (speedup 1.0000x reference)
#include <cuda_runtime.h>

// Problem constants
#define TT   16
#define BB   512
#define NIN  3072
#define SS1  256
#define SS2  256
#define SS3  128
#define EE   8
#define DECAYF 0.95f
#define KCHUNK 512   // reference k-partition hypothesis: 6x512, serial fold

// Persistent scratch / state (allocation-free: __device__ globals)
__device__ float g_H1[(size_t)EE * TT * BB * SS1]; // 67 MB: stage-1 pre-activations, all t
__device__ float g_Hs[(size_t)EE * BB * SS1];      // 4 MB: stage-2/3 pre-activation scratch
__device__ float g_V1[(size_t)EE * BB * SS1];
__device__ float g_V2[(size_t)EE * BB * SS2];
__device__ float g_V3[(size_t)EE * BB * SS3];
__device__ float g_C [(size_t)BB * SS1];           // combined output -> next stage input

// ---------------------------------------------------------------------------
// Zero membrane state + output accumulator
// ---------------------------------------------------------------------------
__global__ void zero_state(float* __restrict__ out, int out_n) {
    int i = blockIdx.x * blockDim.x + threadIdx.x;
    int stride = gridDim.x * blockDim.x;
    const int n12 = EE * BB * SS1;
    for (int j = i; j < n12; j += stride) { g_V1[j] = 0.f; g_V2[j] = 0.f; }
    const int n3 = EE * BB * SS3;
    for (int j = i; j < n3; j += stride) g_V3[j] = 0.f;
    for (int j = i; j < out_n; j += stride) out[j] = 0.f;
}

// ---------------------------------------------------------------------------
// Batched NT SGEMM with k-chunked fp32 accumulation:
//   chunks [0,PC),[PC,2PC),...  each chunk: FRESH accumulator, strictly
//   ascending FMA chain;  C folded serially ascending, ONE rn-add per chunk
//   (C starts 0; 0+P0 exact). Tail chunk (K%PC) folds at the end.
// PC >= K degenerates to the plain serial chain (stages 2/3, K=256).
// 64x64 block tile, BK=32, 256 threads, 4x4 per-thread microtile.
// M,N,K multiples of the tile sizes; no bounds checks.
// ---------------------------------------------------------------------------
__global__ void __launch_bounds__(256) gemm_nt64_panel(
    const float* __restrict__ X,   // [M][K]
    const float* __restrict__ W,   // [E][N][K]
    float* __restrict__ H,         // [E][M][N]
    int M, int N, int K, int PC)   // PC = k-chunk size
{
    const int BM = 64, BN = 64, BK = 32;
    const int e  = blockIdx.z;
    const int m0 = blockIdx.x * BM;
    const int n0 = blockIdx.y * BN;
    const float* Wp = W + (size_t)e * N * K;
    float*       Hp = H + (size_t)e * M * N;

    __shared__ float Xs[BK][BM];
    __shared__ float Ws[BK][BN];

    const int tid = threadIdx.x;
    const int lr  = tid >> 3;         // 0..31 (tile row for loads)
    const int lc  = (tid & 7) << 2;   // 0,4,...,28 (k offset, float4)
    const int ty  = tid >> 4;         // 0..15
    const int tx  = tid & 15;         // 0..15

    float accC[4][4] = {};            // running chunk-fold result
    float accP[4][4] = {};            // current chunk (fresh accumulator)
    int   kb = PC;                    // next chunk boundary (global k index)

    for (int k0 = 0; k0 < K; k0 += BK) {
        #pragma unroll
        for (int r = 0; r < BM; r += 32) {
            float4 v = *reinterpret_cast<const float4*>(
                &X[(size_t)(m0 + lr + r) * K + k0 + lc]);
            Xs[lc + 0][lr + r] = v.x; Xs[lc + 1][lr + r] = v.y;
            Xs[lc + 2][lr + r] = v.z; Xs[lc + 3][lr + r] = v.w;
        }
        #pragma unroll
        for (int r = 0; r < BN; r += 32) {
            float4 v = *reinterpret_cast<const float4*>(
                &Wp[(size_t)(n0 + lr + r) * K + k0 + lc]);
            Ws[lc + 0][lr + r] = v.x; Ws[lc + 1][lr + r] = v.y;
            Ws[lc + 2][lr + r] = v.z; Ws[lc + 3][lr + r] = v.w;
        }
        __syncthreads();

        #pragma unroll
        for (int kk = 0; kk < BK; kk++) {   // strictly ascending k
            float4 xm = *reinterpret_cast<const float4*>(&Xs[kk][ty << 2]);
            float4 wn = *reinterpret_cast<const float4*>(&Ws[kk][tx << 2]);
            float xr[4] = {xm.x, xm.y, xm.z, xm.w};
            float wr[4] = {wn.x, wn.y, wn.z, wn.w};
            #pragma unroll
            for (int i = 0; i < 4; i++)
                #pragma unroll
                for (int j = 0; j < 4; j++)
                    accP[i][j] = __fmaf_rn(xr[i], wr[j], accP[i][j]);

            // Chunk boundary after consuming global k = k0+kk: fold + reset.
            if (k0 + kk + 1 == kb) {
                #pragma unroll
                for (int i = 0; i < 4; i++)
                    #pragma unroll
                    for (int j = 0; j < 4; j++) {
                        accC[i][j] = __fadd_rn(accC[i][j], accP[i][j]);
                        accP[i][j] = 0.f;
                    }
                kb += PC;
            }
        }
        __syncthreads();
    }

    // Tail chunk (K % PC != 0, or K < PC) folds here; if the last fold
    // landed exactly at K, accP is zero and x + 0.0f is bitwise a no-op.
    #pragma unroll
    for (int i = 0; i < 4; i++) {
        float4 v = make_float4(__fadd_rn(accC[i][0], accP[i][0]),
                               __fadd_rn(accC[i][1], accP[i][1]),
                               __fadd_rn(accC[i][2], accP[i][2]),
                               __fadd_rn(accC[i][3], accP[i][3]));
        *reinterpret_cast<float4*>(
            &Hp[(size_t)(m0 + (ty << 2) + i) * N + n0 + (tx << 2)]) = v;
    }
}

// ---------------------------------------------------------------------------
// LIF update + gated expert combine + output time-average accumulation.
// Separate-rounding semantics (confirmed by R2-vs-R4 A/B: reference does
// NOT contract mul+add into FMA):
//   v = rn(rn(v*0.95) + h) ; spk = (v >= 1) ; v = rn(v - spk)
//   c = sum_e g[e]*spk   (exact: multiples of 1/64, any order)
//   Osum += c/16         (exact dyadic adds)
// ---------------------------------------------------------------------------
__global__ void lif_combine(
    const float* __restrict__ H, size_t h_off, size_t h_estride,
    float* __restrict__ V,
    const float* __restrict__ g,
    float* __restrict__ C,            // next-stage input (null for stage 3)
    float* __restrict__ Osum,         // += c / T
    int n)                            // n = B*O (also V expert stride)
{
    int idx = blockIdx.x * blockDim.x + threadIdx.x;
    if (idx >= n) return;
    float c = 0.f;
    #pragma unroll
    for (int e = 0; e < EE; e++) {
        size_t hi = h_off + (size_t)e * h_estride + idx;
        size_t vi = (size_t)e * n + idx;
        float v   = __fadd_rn(__fmul_rn(V[vi], DECAYF), H[hi]);
        float spk = (v >= 1.0f) ? 1.0f : 0.0f;
        V[vi] = __fsub_rn(v, spk);
        c = __fadd_rn(c, __fmul_rn(__ldg(&g[e]), spk));
    }
    if (C) C[idx] = c;
    Osum[idx] = __fadd_rn(Osum[idx], __fmul_rn(c, (1.0f / (float)TT)));
}

// ---------------------------------------------------------------------------
extern "C" void kernel_launch(void* const* d_in, const int* in_sizes, int n_in,
                              void* d_out, int out_size) {
    const float* X  = (const float*)d_in[0];  // [16][512][3072]
    const float* W1 = (const float*)d_in[1];  // [8][256][3072]
    const float* W2 = (const float*)d_in[2];  // [8][256][256]
    const float* W3 = (const float*)d_in[3];  // [8][128][256]
    const float* g1 = (const float*)d_in[4];
    const float* g2 = (const float*)d_in[5];
    const float* g3 = (const float*)d_in[6];
    float* out = (float*)d_out;

    float *H1, *Hs, *V1, *V2, *V3, *C;
    cudaGetSymbolAddress((void**)&H1, g_H1);
    cudaGetSymbolAddress((void**)&Hs, g_Hs);
    cudaGetSymbolAddress((void**)&V1, g_V1);
    cudaGetSymbolAddress((void**)&V2, g_V2);
    cudaGetSymbolAddress((void**)&V3, g_V3);
    cudaGetSymbolAddress((void**)&C,  g_C);

    // Zero states + output accumulator (output is poisoned by the harness).
    zero_state<<<512, 256>>>(out, out_size);

    // Stage 1 for ALL timesteps in one batched GEMM (time-independent):
    // M = T*B = 8192, N = 256, K = 3072, E = 8.
    // k-chunks of 512: 6 fresh chains, serial ascending fold.
    {
        dim3 grid(TT * BB / 64, SS1 / 64, EE);
        gemm_nt64_panel<<<grid, 256>>>(X, W1, H1, TT * BB, SS1, NIN, KCHUNK);
    }

    float* out1 = out;
    float* out2 = out + BB * SS1;
    float* out3 = out + BB * SS1 + BB * SS2;

    for (int t = 0; t < TT; t++) {
        // Stage 1 LIF + combine (reads slice t of H1)
        lif_combine<<<(BB * SS1 + 255) / 256, 256>>>(
            H1, (size_t)t * BB * SS1, (size_t)TT * BB * SS1,
            V1, g1, C, out1, BB * SS1);

        // Stage 2 GEMM: M=512, N=256, K=256 < 512 -> single serial chain
        {
            dim3 grid(BB / 64, SS2 / 64, EE);
            gemm_nt64_panel<<<grid, 256>>>(C, W2, Hs, BB, SS2, SS1, KCHUNK);
        }
        lif_combine<<<(BB * SS2 + 255) / 256, 256>>>(
            Hs, 0, (size_t)BB * SS2, V2, g2, C, out2, BB * SS2);

        // Stage 3 GEMM: M=512, N=128, K=256 < 512 -> single serial chain
        {
            dim3 grid(BB / 64, SS3 / 64, EE);
            gemm_nt64_panel<<<grid, 256>>>(C, W3, Hs, BB, SS3, SS2, KCHUNK);
        }
        lif_combine<<<(BB * SS3 + 255) / 256, 256>>>(
            Hs, 0, (size_t)BB * SS3, V3, g3, nullptr, out3, BB * SS3);
    }
}